// round 1
// baseline (speedup 1.0000x reference)
#include <cuda_runtime.h>

// AnalyticalBoundedLineAttractor — analytic piecewise-affine ODE integrator.
//
// Per step (per batch element):
//   z = W x + b ; m = (z > 0)
//   Z = DT * (diag(m) W - I) ; v = DT * (m .* b)
//   x_next = e^Z x + phi1(Z) v   computed via augmented Taylor series:
//     p1 = Z x + v ; p_k = Z p_{k-1} / k ; x_next = x + sum_k p_k
//   Z p = DT * (m .* (W p) - p)  -> one 64x64 mat-vec per term.
//
// Thread i owns row i of W (64 registers). p-vector lives in shared
// (double-buffered), read as float4 broadcasts. 2 batch elements per
// 128-thread CTA (warps 0,1 -> elem0; warps 2,3 -> elem1) so warps cover
// all 4 SMSPs. grid = batch/2 = 128 CTAs -> single wave on GB300.

#define DIMV   64
#define KTERMS 6        // highest Taylor power; trunc err ~ 0.16^7/7! ~ 6e-9/step
#define DTC    0.05f

__global__ void __launch_bounds__(128, 1)
attractor_kernel(const float* __restrict__ x0,
                 const float* __restrict__ Wg,
                 const float* __restrict__ bg,
                 float* __restrict__ out,
                 int tsteps)
{
    __shared__ __align__(16) float ps[2][2][DIMV];   // [elem][buf][i]

    const int tid  = threadIdx.x;
    const int el   = tid >> 6;        // local element 0/1
    const int i    = tid & 63;        // row index
    const int elem = blockIdx.x * 2 + el;

    // ---- load W row i into registers (16 x LDG.128) ----
    float w[DIMV];
    const float4* wrow = reinterpret_cast<const float4*>(Wg + i * DIMV);
#pragma unroll
    for (int q = 0; q < 16; q++) {
        float4 t = wrow[q];
        w[4*q+0] = t.x; w[4*q+1] = t.y; w[4*q+2] = t.z; w[4*q+3] = t.w;
    }
    const float b_r = bg[i];
    float xi = x0[(size_t)elem * DIMV + i];

    float* pbase = &ps[el][0][0];     // buffers at pbase + 64*buf
    pbase[i] = xi;                    // buf 0 holds x
    float* outp = out + (size_t)elem * tsteps * DIMV + i;
    __syncthreads();

    // dot(row_i_of_W, buf) with 8 accumulators, float4 broadcast LDS
    auto dot = [&](const float* buf) -> float {
        const float4* p4 = reinterpret_cast<const float4*>(buf);
        float a0 = 0.f, a1 = 0.f, a2 = 0.f, a3 = 0.f;
        float a4 = 0.f, a5 = 0.f, a6 = 0.f, a7 = 0.f;
#pragma unroll
        for (int q = 0; q < 16; q += 2) {
            float4 v0 = p4[q];
            float4 v1 = p4[q + 1];
            a0 += w[4*q+0] * v0.x;  a1 += w[4*q+1] * v0.y;
            a2 += w[4*q+2] * v0.z;  a3 += w[4*q+3] * v0.w;
            a4 += w[4*q+4] * v1.x;  a5 += w[4*q+5] * v1.y;
            a6 += w[4*q+6] * v1.z;  a7 += w[4*q+7] * v1.w;
        }
        return ((a0 + a1) + (a2 + a3)) + ((a4 + a5) + (a6 + a7));
    };

    const float invk[KTERMS + 1] = { 0.f, 0.f, 1.f/2.f, 1.f/3.f,
                                     1.f/4.f, 1.f/5.f, 1.f/6.f };

    int cb = 0;  // buffer holding current x
    for (int t = 0; t < tsteps; t++) {
        outp[t * DIMV] = xi;                      // trajectory stores x BEFORE update

        // term 1: wx doubles as mask pre-activation and p1 ingredient
        float wx = dot(pbase + (cb << 6));
        float m  = (wx + b_r) > 0.f ? 1.f : 0.f;
        float p  = DTC * (m * wx - xi) + DTC * m * b_r;   // p1 = Zx + v
        float sum = xi + p;
        int rb = cb ^ 1;
        pbase[(rb << 6) + i] = p;
        __syncthreads();

        // terms k = 2 .. KTERMS-1 (write + 1 barrier each)
#pragma unroll
        for (int k = 2; k < KTERMS; k++) {
            float tk = dot(pbase + (rb << 6));
            p = DTC * (m * tk - p) * invk[k];
            sum += p;
            rb ^= 1;
            pbase[(rb << 6) + i] = p;
            __syncthreads();
        }

        // final term k = KTERMS: no shared write needed
        {
            float tk = dot(pbase + (rb << 6));
            p = DTC * (m * tk - p) * invk[KTERMS];
            sum += p;
        }

        xi = sum;
        cb = rb ^ 1;                  // that buffer's readers all done -> safe
        pbase[(cb << 6) + i] = xi;
        __syncthreads();
    }
}

extern "C" void kernel_launch(void* const* d_in, const int* in_sizes, int n_in,
                              void* d_out, int out_size)
{
    const float* x0 = (const float*)d_in[0];   // (batch, 64)
    const float* W  = (const float*)d_in[1];   // (64, 64)
    const float* b  = (const float*)d_in[2];   // (64,)
    float* out = (float*)d_out;                // (batch, T, 64)

    int batch  = in_sizes[0] / DIMV;           // 256
    int tsteps = out_size / (batch * DIMV);    // 100

    attractor_kernel<<<batch / 2, 128>>>(x0, W, b, out, tsteps);
}

// round 2
// speedup vs baseline: 1.5512x; 1.5512x over previous
#include <cuda_runtime.h>

// AnalyticalBoundedLineAttractor — analytic piecewise-affine ODE integrator.
//
// Per step: z = Wx + b; m = (z>0); x' = e^Z x + phi1(Z) v with
// Z = DT(diag(m)W - I), v = DT(m.*b), via augmented Taylor recurrence
//   p1 = Zx + v ; p_k = Z p_{k-1}/k ; x' = x + sum p_k   (K = 4 terms;
//   truncation ~||Z||^5/5! ~ 6e-7/step -> ~1e-4 global, gate is 1e-3)
// Z p = DT(m .* (W p) - p): one 64x64 mat-vec per term.
//
// Thread i owns row i of W packed as 32 f32x2 register pairs; dots use
// sm_103a packed fma.rn.f32x2 (half the fma-pipe slots of scalar FFMA,
// ptxas never auto-fuses). p lives in shared (double-buffered), read as
// 128-bit broadcasts. 2 elements per 128-thread CTA on separate named
// 64-thread barriers so they never wait on each other. grid = 128 CTAs
// -> single wave, every latency chain concurrent.

#define DIMV 64
#define DTC  0.05f

using u64 = unsigned long long;

__device__ __forceinline__ u64 fma2(u64 a, u64 b, u64 c) {
    u64 d; asm("fma.rn.f32x2 %0, %1, %2, %3;" : "=l"(d) : "l"(a), "l"(b), "l"(c));
    return d;
}
__device__ __forceinline__ u64 add2(u64 a, u64 b) {
    u64 d; asm("add.rn.f32x2 %0, %1, %2;" : "=l"(d) : "l"(a), "l"(b));
    return d;
}

__global__ void __launch_bounds__(128, 1)
attractor_kernel(const float* __restrict__ x0,
                 const float* __restrict__ Wg,
                 const float* __restrict__ bg,
                 float* __restrict__ out,
                 int tsteps)
{
    __shared__ __align__(16) float ps[2][2][DIMV];   // [elem][buf][i]

    const int tid  = threadIdx.x;
    const int el   = tid >> 6;        // local element 0/1
    const int i    = tid & 63;        // row index
    const int elem = blockIdx.x * 2 + el;
    const int bar  = el + 1;          // named barrier id per element

    // ---- W row i as 32 packed f32x2 pairs (memory pair order == f32x2 lanes) ----
    u64 w2[32];
    const ulonglong2* wrow = reinterpret_cast<const ulonglong2*>(Wg + i * DIMV);
#pragma unroll
    for (int q = 0; q < 16; q++) {
        ulonglong2 t = wrow[q];
        w2[2*q]   = t.x;
        w2[2*q+1] = t.y;
    }
    const float b_r = bg[i];
    float xi = x0[(size_t)elem * DIMV + i];

    float* pbase = &ps[el][0][0];     // buffers at pbase + 64*buf
    pbase[i] = xi;                    // buf 0 holds x
    float* outp = out + (size_t)elem * tsteps * DIMV + i;
    asm volatile("bar.sync %0, 64;" :: "r"(bar) : "memory");

    // dot(W_row_i, buf): 16 x LDS.128 + 32 x fma.f32x2, 4 packed accumulators
    auto dot = [&](const float* buf) -> float {
        const ulonglong2* p16 = reinterpret_cast<const ulonglong2*>(buf);
        u64 a0 = 0ull, a1 = 0ull, a2 = 0ull, a3 = 0ull;
#pragma unroll
        for (int q = 0; q < 16; q += 2) {
            ulonglong2 v0 = p16[q];
            ulonglong2 v1 = p16[q + 1];
            a0 = fma2(w2[2*q + 0], v0.x, a0);
            a1 = fma2(w2[2*q + 1], v0.y, a1);
            a2 = fma2(w2[2*q + 2], v1.x, a2);
            a3 = fma2(w2[2*q + 3], v1.y, a3);
        }
        u64 s = add2(add2(a0, a1), add2(a2, a3));
        float lo, hi;
        asm("mov.b64 {%0, %1}, %2;" : "=f"(lo), "=f"(hi) : "l"(s));
        return lo + hi;
    };

#pragma unroll 1
    for (int t = 0; t < tsteps; t++) {
        outp[t * DIMV] = xi;                      // trajectory stores x BEFORE update

        // term 1: wx is both mask pre-activation and p1 ingredient (x in buf 0)
        float wx = dot(pbase);
        float z  = wx + b_r;
        float m  = z > 0.f ? 1.f : 0.f;
        float p  = DTC * (m * z - xi);            // p1 = Zx + v
        float sum = xi + p;
        pbase[64 + i] = p;                        // write buf 1
        asm volatile("bar.sync %0, 64;" :: "r"(bar) : "memory");

        // term 2: read buf 1, write buf 0 (x fully consumed by term 1)
        float t2 = dot(pbase + 64);
        p = DTC * (m * t2 - p) * 0.5f;
        sum += p;
        pbase[i] = p;
        asm volatile("bar.sync %0, 64;" :: "r"(bar) : "memory");

        // term 3: read buf 0, write buf 1
        float t3 = dot(pbase);
        p = DTC * (m * t3 - p) * (1.f / 3.f);
        sum += p;
        pbase[64 + i] = p;
        asm volatile("bar.sync %0, 64;" :: "r"(bar) : "memory");

        // term 4: read buf 1, no write
        float t4 = dot(pbase + 64);
        p = DTC * (m * t4 - p) * 0.25f;
        sum += p;

        // new x into buf 0 (term-3 barrier already retired all buf-0 reads)
        xi = sum;
        pbase[i] = xi;
        asm volatile("bar.sync %0, 64;" :: "r"(bar) : "memory");
    }
}

extern "C" void kernel_launch(void* const* d_in, const int* in_sizes, int n_in,
                              void* d_out, int out_size)
{
    const float* x0 = (const float*)d_in[0];   // (batch, 64)
    const float* W  = (const float*)d_in[1];   // (64, 64)
    const float* b  = (const float*)d_in[2];   // (64,)
    float* out = (float*)d_out;                // (batch, T, 64)

    int batch  = in_sizes[0] / DIMV;           // 256
    int tsteps = out_size / (batch * DIMV);    // 100

    attractor_kernel<<<batch / 2, 128>>>(x0, W, b, out, tsteps);
}

// round 3
// speedup vs baseline: 1.9736x; 1.2723x over previous
#include <cuda_runtime.h>

// AnalyticalBoundedLineAttractor — analytic piecewise-affine ODE integrator.
//
// Per step: z = Wx + b; m = (z>0); x' = e^Z x + phi1(Z) v with
// Z = DT(diag(m)W - I), v = DT(m.*b), via augmented Taylor recurrence
//   p1 = Zx + v = DT*(relu(z) - x) ; p_k = Z p_{k-1}/k ; x' = x + sum p_k
// K = 3 terms: worst-case truncation ||Z||^4/4! ~ 2e-6/step -> <= 2e-4
// global (gate 1e-3); measured K=6 vs K=4 delta was ~1e-8, so expected ~1e-5.
//
// Z p = m .* (W' p) - DT*p  with W' = DT*W pre-scaled into registers.
//
// Latency-chain kernel (all 256 chains concurrent; wall time = chain length).
// Thread i owns row i of W' as 32 packed f32x2 regs; dots use sm_103a
// fma.rn.f32x2 (half the fma-pipe slots, ptxas never auto-fuses). p is
// double-buffered in shared, read as 128-bit broadcasts. 2 elements per
// 128-thread CTA on separate named 64-thread barriers. 3 exchanges ->
// 3 barriers per step (minimum for 3 sequential matvecs).

#define DIMV 64
#define DTC  0.05f

using u64 = unsigned long long;

__device__ __forceinline__ u64 fma2(u64 a, u64 b, u64 c) {
    u64 d; asm("fma.rn.f32x2 %0, %1, %2, %3;" : "=l"(d) : "l"(a), "l"(b), "l"(c));
    return d;
}
__device__ __forceinline__ u64 add2(u64 a, u64 b) {
    u64 d; asm("add.rn.f32x2 %0, %1, %2;" : "=l"(d) : "l"(a), "l"(b));
    return d;
}

__global__ void __launch_bounds__(128, 1)
attractor_kernel(const float* __restrict__ x0,
                 const float* __restrict__ Wg,
                 const float* __restrict__ bg,
                 float* __restrict__ out,
                 int tsteps)
{
    __shared__ __align__(16) float ps[2][2][DIMV];   // [elem][buf][i]

    const int tid  = threadIdx.x;
    const int el   = tid >> 6;        // local element 0/1
    const int i    = tid & 63;        // row index
    const int elem = blockIdx.x * 2 + el;
    const int bar  = el + 1;          // named barrier id per element

    // ---- W row i, pre-scaled by DT, as 32 packed f32x2 pairs ----
    u64 w2[32];
    {
        const float* wrow = Wg + i * DIMV;
#pragma unroll
        for (int q = 0; q < 16; q++) {
            float4 t = reinterpret_cast<const float4*>(wrow)[q];
            float s0 = t.x * DTC, s1 = t.y * DTC, s2 = t.z * DTC, s3 = t.w * DTC;
            asm("mov.b64 %0, {%1, %2};" : "=l"(w2[2*q])   : "f"(s0), "f"(s1));
            asm("mov.b64 %0, {%1, %2};" : "=l"(w2[2*q+1]) : "f"(s2), "f"(s3));
        }
    }
    const float b_r = bg[i];
    float xi = x0[(size_t)elem * DIMV + i];

    float* pbase = &ps[el][0][0];     // buffers at pbase + 64*buf
    pbase[i] = xi;                    // buf 0 holds x initially
    float* outp = out + (size_t)elem * tsteps * DIMV + i;
    asm volatile("bar.sync %0, 64;" :: "r"(bar) : "memory");

    // dot(DT*W_row_i, buf): 16 x LDS.128 + 32 x fma.f32x2, 4 packed accs
    auto dot = [&](const float* buf) -> float {
        const ulonglong2* p16 = reinterpret_cast<const ulonglong2*>(buf);
        u64 a0 = 0ull, a1 = 0ull, a2 = 0ull, a3 = 0ull;
#pragma unroll
        for (int q = 0; q < 16; q += 2) {
            ulonglong2 v0 = p16[q];
            ulonglong2 v1 = p16[q + 1];
            a0 = fma2(w2[2*q + 0], v0.x, a0);
            a1 = fma2(w2[2*q + 1], v0.y, a1);
            a2 = fma2(w2[2*q + 2], v1.x, a2);
            a3 = fma2(w2[2*q + 3], v1.y, a3);
        }
        u64 s = add2(add2(a0, a1), add2(a2, a3));
        float lo, hi;
        asm("mov.b64 {%0, %1}, %2;" : "=f"(lo), "=f"(hi) : "l"(s));
        return lo + hi;
    };

    int cb = 0;   // buffer currently holding x
#pragma unroll 1
    for (int t = 0; t < tsteps; t++) {
        outp[t * DIMV] = xi;                    // trajectory stores x BEFORE update
        const int nb = cb ^ 1;

        // term 1: dwx = DT*(Wx); z-sign decides mask; p1 = DT*(relu(z) - x)
        float dwx = dot(pbase + (cb << 6));
        float z   = dwx + DTC * b_r;            // DT*z has same sign as z
        bool  m   = z > 0.f;
        float p   = (m ? z : 0.f) - DTC * xi;   // p1 = DT*(m*(Wx+b) - x)
        float sum = xi + p;
        pbase[(nb << 6) + i] = p;
        asm volatile("bar.sync %0, 64;" :: "r"(bar) : "memory");

        // term 2: p2 = (m .* (W' p1) - DT*p1) / 2
        float t2 = dot(pbase + (nb << 6));
        p = ((m ? t2 : 0.f) - DTC * p) * 0.5f;
        sum += p;
        pbase[(cb << 6) + i] = p;               // dot1 readers of buf cb retired at bar
        asm volatile("bar.sync %0, 64;" :: "r"(bar) : "memory");

        // term 3: p3 = (m .* (W' p2) - DT*p2) / 3   (no shared write)
        float t3 = dot(pbase + (cb << 6));
        p = ((m ? t3 : 0.f) - DTC * p) * (1.f / 3.f);
        xi = sum + p;

        pbase[(nb << 6) + i] = xi;              // dot2 readers of buf nb retired at bar
        asm volatile("bar.sync %0, 64;" :: "r"(bar) : "memory");
        cb = nb;
    }
}

extern "C" void kernel_launch(void* const* d_in, const int* in_sizes, int n_in,
                              void* d_out, int out_size)
{
    const float* x0 = (const float*)d_in[0];   // (batch, 64)
    const float* W  = (const float*)d_in[1];   // (64, 64)
    const float* b  = (const float*)d_in[2];   // (64,)
    float* out = (float*)d_out;                // (batch, T, 64)

    int batch  = in_sizes[0] / DIMV;           // 256
    int tsteps = out_size / (batch * DIMV);    // 100

    attractor_kernel<<<batch / 2, 128>>>(x0, W, b, out, tsteps);
}

// round 4
// speedup vs baseline: 2.5795x; 1.3070x over previous
#include <cuda_runtime.h>

// AnalyticalBoundedLineAttractor — analytic piecewise-affine ODE integrator.
//
// Per step: z = Wx + b; m = (z>0); x' = e^Z x + phi1(Z) v with
// Z = DT(diag(m)W - I), v = DT(m.*b), via augmented Taylor recurrence
//   p1 = Zx + v = DT*(relu(z) - x) ; p2 = Z p1 / 2 ; x' = x + p1 + p2.
// K = 2 terms: measurement-calibrated truncation (K4->K3 global delta was
// 7.4e-6; per-term ratio (k+1)/||Z||_eff ~ 20-45x) predicts global rel_err
// ~1.5-3.5e-4 against a 1e-3 gate; dynamics are contractive (e^{-DT}/step)
// so local errors decay rather than compound.
//
// Z p = m .* (W' p) - DT*p  with W' = DT*W pre-scaled into registers.
//
// Latency-chain kernel: wall time = single-chain latency, so everything
// targets the serial path. One element per 64-thread CTA (grid=256, all
// resident in one wave) so sync is plain HW BAR.SYNC (floor ~7 cyc,
// native STS drain) instead of named barriers (~47 cyc effective).
// Thread i owns row i of W' as 32 packed f32x2 regs; dots use sm_103a
// fma.rn.f32x2 (ptxas never auto-fuses). p exchanged through shared,
// read as 128-bit broadcasts. 2 dots + 2 barriers per step.

#define DIMV 64
#define DTC  0.05f

using u64 = unsigned long long;

__device__ __forceinline__ u64 fma2(u64 a, u64 b, u64 c) {
    u64 d; asm("fma.rn.f32x2 %0, %1, %2, %3;" : "=l"(d) : "l"(a), "l"(b), "l"(c));
    return d;
}
__device__ __forceinline__ u64 add2(u64 a, u64 b) {
    u64 d; asm("add.rn.f32x2 %0, %1, %2;" : "=l"(d) : "l"(a), "l"(b));
    return d;
}

__global__ void __launch_bounds__(64, 1)
attractor_kernel(const float* __restrict__ x0,
                 const float* __restrict__ Wg,
                 const float* __restrict__ bg,
                 float* __restrict__ out,
                 int tsteps)
{
    __shared__ __align__(16) float xs[DIMV];    // current x
    __shared__ __align__(16) float p1s[DIMV];   // term-1 vector

    const int i    = threadIdx.x;               // row index
    const int elem = blockIdx.x;

    // ---- W row i, pre-scaled by DT, as 32 packed f32x2 pairs ----
    u64 w2[32];
    {
        const float* wrow = Wg + i * DIMV;
#pragma unroll
        for (int q = 0; q < 16; q++) {
            float4 t = reinterpret_cast<const float4*>(wrow)[q];
            float s0 = t.x * DTC, s1 = t.y * DTC, s2 = t.z * DTC, s3 = t.w * DTC;
            asm("mov.b64 %0, {%1, %2};" : "=l"(w2[2*q])   : "f"(s0), "f"(s1));
            asm("mov.b64 %0, {%1, %2};" : "=l"(w2[2*q+1]) : "f"(s2), "f"(s3));
        }
    }
    const float db = DTC * bg[i];               // DT * b_i
    float xi = x0[(size_t)elem * DIMV + i];

    xs[i] = xi;
    float* outp = out + (size_t)elem * tsteps * DIMV + i;
    __syncthreads();

    // dot(DT*W_row_i, buf): 16 x LDS.128 + 32 x fma.f32x2, 4 packed accs
    auto dot = [&](const float* buf) -> float {
        const ulonglong2* p16 = reinterpret_cast<const ulonglong2*>(buf);
        u64 a0 = 0ull, a1 = 0ull, a2 = 0ull, a3 = 0ull;
#pragma unroll
        for (int q = 0; q < 16; q += 2) {
            ulonglong2 v0 = p16[q];
            ulonglong2 v1 = p16[q + 1];
            a0 = fma2(w2[2*q + 0], v0.x, a0);
            a1 = fma2(w2[2*q + 1], v0.y, a1);
            a2 = fma2(w2[2*q + 2], v1.x, a2);
            a3 = fma2(w2[2*q + 3], v1.y, a3);
        }
        u64 s = add2(add2(a0, a1), add2(a2, a3));
        float lo, hi;
        asm("mov.b64 {%0, %1}, %2;" : "=f"(lo), "=f"(hi) : "l"(s));
        return lo + hi;
    };

#pragma unroll 1
    for (int t = 0; t < tsteps; t++) {
        outp[t * DIMV] = xi;                    // trajectory stores x BEFORE update

        // term 1: dwx = DT*(Wx); sign(z) == sign(DT*z); p1 = DT*(relu(z) - x)
        float dwx = dot(xs);
        float z   = dwx + db;
        bool  m   = z > 0.f;
        float p   = (m ? z : 0.f) - DTC * xi;   // p1
        float sum = xi + p;
        p1s[i] = p;
        __syncthreads();                        // also retires all xs readers

        // term 2: p2 = (m .* (W' p1) - DT*p1) / 2 ; x' = x + p1 + p2
        float t2 = dot(p1s);
        xi = sum + ((m ? t2 : 0.f) - DTC * p) * 0.5f;

        xs[i] = xi;                             // safe: xs readers retired above
        __syncthreads();
    }
}

extern "C" void kernel_launch(void* const* d_in, const int* in_sizes, int n_in,
                              void* d_out, int out_size)
{
    const float* x0 = (const float*)d_in[0];   // (batch, 64)
    const float* W  = (const float*)d_in[1];   // (64, 64)
    const float* b  = (const float*)d_in[2];   // (64,)
    float* out = (float*)d_out;                // (batch, T, 64)

    int batch  = in_sizes[0] / DIMV;           // 256
    int tsteps = out_size / (batch * DIMV);    // 100

    attractor_kernel<<<batch, 64>>>(x0, W, b, out, tsteps);
}